// round 4
// baseline (speedup 1.0000x reference)
#include <cuda_runtime.h>
#include <math.h>
#include <stdint.h>

// Problem constants (fixed-shape problem)
#define Nn   20000
#define Ee   100000
#define Ll   4
#define Dd   64
#define Hh   8
#define HIDc 512

// mma.sync tf32 LSTM tiling
#define BM   128        // edges per CTA
#define BNH  32         // hidden units per CTA -> 128 gate columns
#define BK   32         // K per chunk
#define LDSW 36         // smem row stride in words (32 + 4 pad: conflict-free frags)
#define TILE_WORDS (BM * LDSW)                 // 4608
#define DYN_SMEM   (4 * TILE_WORDS * 4)       // 2 bufs x (A+B) = 73728 B

// ---------------- scratch (device globals; no allocation allowed) ----------
__device__ float g_h0[(size_t)Ee * HIDc];
__device__ float g_h1[(size_t)Ee * HIDc];
__device__ float g_c [(size_t)Ee * HIDc];
__device__ float g_a [(size_t)Ee * Hh];
__device__ float g_amax[(size_t)Nn * Hh];
__device__ float g_den [(size_t)Nn * Hh];

// ---------------- helpers ----------------------------------------------------
__device__ __forceinline__ uint32_t f2tf(float f) {
    uint32_t r;
    asm("cvt.rna.tf32.f32 %0, %1;" : "=r"(r) : "f"(f));
    return r;
}
__device__ __forceinline__ void mma8(float* d, const uint32_t* a,
                                     uint32_t b0, uint32_t b1) {
    asm volatile(
        "mma.sync.aligned.m16n8k8.row.col.f32.tf32.tf32.f32 "
        "{%0,%1,%2,%3}, {%4,%5,%6,%7}, {%8,%9}, {%0,%1,%2,%3};"
        : "+f"(d[0]), "+f"(d[1]), "+f"(d[2]), "+f"(d[3])
        : "r"(a[0]), "r"(a[1]), "r"(a[2]), "r"(a[3]), "r"(b0), "r"(b1));
}

// ---------------- init -------------------------------------------------------
__global__ void init_kernel(float* __restrict__ out) {
    int i = blockIdx.x * blockDim.x + threadIdx.x;
    if (i < Nn * HIDc) out[i] = 0.f;
    if (i < Nn * Hh) {
        g_amax[i] = __int_as_float(0xFF800000);
        g_den[i]  = 0.f;
    }
}

// ---------------- tensor-core (mma.sync tf32) LSTM step ----------------------
// gates(E x 2048) = x_t @ W_ih^T + h_prev @ W_hh^T (+bias in epilogue).
// CTA: 128 edges x 32 hidden (x4 gates = 128 gate cols), K double-buffered by 32.
// Warp (8 warps: 4 along M x 2 along Nh): 32 rows x 16 hidden x 4 gates.
// B smem column c = gate(c>>5)*32 + local_hidden(c&31); weight row = g*512+hid.
__global__ __launch_bounds__(256, 1)
void lstm_mma_kernel(const float* __restrict__ feat,
                     const int*   __restrict__ idx,
                     const float* __restrict__ Wih,
                     const float* __restrict__ Whh,
                     const float* __restrict__ bih,
                     const float* __restrict__ bhh,
                     int t)
{
    extern __shared__ uint32_t smem[];
    __shared__ int   rows_s[BM];
    __shared__ float bias_s[128];

    const int tid   = threadIdx.x;
    const int wid   = tid >> 5;
    const int lane  = tid & 31;
    const int warpM = wid & 3;        // 0..3 (rows)
    const int warpN = wid >> 2;       // 0..1 (hidden halves)
    const int e0    = blockIdx.x * BM;
    const int nh0   = blockIdx.y * BNH;

    const float* hprev = (t & 1) ? g_h0 : g_h1;
    float*       hnext = (t & 1) ? g_h1 : g_h0;
    const bool   first = (t == 0);
    const int    NC    = first ? 2 : 18;      // K chunks: 64 feat (+512 hidden)

    // shared init
    if (tid < BM) {
        int e = e0 + tid; if (e >= Ee) e = Ee - 1;
        rows_s[tid] = idx[e * Ll + t];
    }
    if (tid < 128) {   // bias, c = g*32 + hh
        int g = tid >> 5, hh = tid & 31;
        int r = g * HIDc + nh0 + hh;
        bias_s[tid] = bih[r] + bhh[r];
    }

    // fill-lane mapping: row r, k-half kh (16 floats = 4 float4 each for A and B)
    const int r     = tid & 127;
    const int kh    = (tid >> 7) & 1;
    const int k0loc = kh * 16;
    const int bg    = r >> 5, bhh_ = r & 31;
    const int wrow  = bg * HIDc + nh0 + bhh_;

    float4 va[4], vb[4];
    auto load_regs = [&](int kc) {
        const float* ap;
        if (kc < 2) {
            ap = feat + (size_t)rows_s[r] * Dd + kc * BK + k0loc;
        } else {
            int e = e0 + r; if (e >= Ee) e = Ee - 1;
            ap = hprev + (size_t)e * HIDc + (kc - 2) * BK + k0loc;
        }
        const float* bp = (kc < 2)
            ? Wih + (size_t)wrow * Dd   + kc * BK + k0loc
            : Whh + (size_t)wrow * HIDc + (kc - 2) * BK + k0loc;
#pragma unroll
        for (int q = 0; q < 4; q++) {
            va[q] = __ldg((const float4*)(ap) + q);
            vb[q] = __ldg((const float4*)(bp) + q);
        }
    };
    auto store_stage = [&](int buf) {
        uint32_t* da = smem + buf * TILE_WORDS + r * LDSW + k0loc;
        uint32_t* db = da + 2 * TILE_WORDS;
#pragma unroll
        for (int q = 0; q < 4; q++) {
            uint4 ua = make_uint4(f2tf(va[q].x), f2tf(va[q].y), f2tf(va[q].z), f2tf(va[q].w));
            uint4 ub = make_uint4(f2tf(vb[q].x), f2tf(vb[q].y), f2tf(vb[q].z), f2tf(vb[q].w));
            *(uint4*)(da + q * 4) = ua;
            *(uint4*)(db + q * 4) = ub;
        }
    };

    float acc[2][2][4][4];
#pragma unroll
    for (int mb = 0; mb < 2; mb++)
#pragma unroll
        for (int nb = 0; nb < 2; nb++)
#pragma unroll
            for (int g = 0; g < 4; g++)
#pragma unroll
                for (int v = 0; v < 4; v++) acc[mb][nb][g][v] = 0.f;

    __syncthreads();                 // rows_s ready
    load_regs(0);
    store_stage(0);
    __syncthreads();

    const int arow = warpM * 32 + (lane >> 2);
    const int kl   = lane & 3;

    for (int kc = 0; kc < NC; kc++) {
        const int buf = kc & 1;
        if (kc + 1 < NC) load_regs(kc + 1);

        const uint32_t* Ab = smem + buf * TILE_WORDS;
        const uint32_t* Bb = Ab + 2 * TILE_WORDS;
#pragma unroll
        for (int kk = 0; kk < 4; kk++) {
            uint32_t afr[2][4];
#pragma unroll
            for (int mb = 0; mb < 2; mb++) {
                const uint32_t* A0 = Ab + (arow + mb * 16) * LDSW + kk * 8 + kl;
                afr[mb][0] = A0[0];
                afr[mb][1] = A0[8 * LDSW];
                afr[mb][2] = A0[4];
                afr[mb][3] = A0[8 * LDSW + 4];
            }
#pragma unroll
            for (int nb = 0; nb < 2; nb++) {
                int colb = warpN * 16 + nb * 8 + (lane >> 2);
#pragma unroll
                for (int g = 0; g < 4; g++) {
                    const uint32_t* B0 = Bb + (g * 32 + colb) * LDSW + kk * 8 + kl;
                    uint32_t b0 = B0[0], b1 = B0[4];
                    mma8(acc[0][nb][g], afr[0], b0, b1);
                    mma8(acc[1][nb][g], afr[1], b0, b1);
                }
            }
        }
        if (kc + 1 < NC) {
            __syncthreads();
            store_stage((kc + 1) & 1);
            __syncthreads();
        }
    }

    // ---- epilogue: LSTM cell from accumulators ------------------------------
#pragma unroll
    for (int mb = 0; mb < 2; mb++) {
#pragma unroll
        for (int rh = 0; rh < 2; rh++) {
            int e = e0 + warpM * 32 + mb * 16 + (lane >> 2) + rh * 8;
            if (e >= Ee) continue;
            float* cp = g_c   + (size_t)e * HIDc + nh0;
            float* hp = hnext + (size_t)e * HIDc + nh0;
#pragma unroll
            for (int nb = 0; nb < 2; nb++) {
                int hh = warpN * 16 + nb * 8 + (lane & 3) * 2;
                float2 cold = make_float2(0.f, 0.f);
                if (!first) cold = *(const float2*)(cp + hh);
                float cv[2], hv[2];
#pragma unroll
                for (int v = 0; v < 2; v++) {
                    int ci = rh * 2 + v;
                    float gi = acc[mb][nb][0][ci] + bias_s[      hh + v];
                    float gf = acc[mb][nb][1][ci] + bias_s[ 32 + hh + v];
                    float gg = acc[mb][nb][2][ci] + bias_s[ 64 + hh + v];
                    float go = acc[mb][nb][3][ci] + bias_s[ 96 + hh + v];
                    float si = 1.f / (1.f + __expf(-gi));
                    float sf = 1.f / (1.f + __expf(-gf));
                    float tg = tanhf(gg);
                    float so = 1.f / (1.f + __expf(-go));
                    float co = v ? cold.y : cold.x;
                    float cn = sf * co + si * tg;
                    cv[v] = cn;
                    hv[v] = so * tanhf(cn);
                }
                *(float2*)(cp + hh) = make_float2(cv[0], cv[1]);
                *(float2*)(hp + hh) = make_float2(hv[0], hv[1]);
            }
        }
    }
}

// ---------------- attention logits + segment max (warp per edge) -----------
__global__ void attn_logits_kernel(const float* __restrict__ feat,
                                   const int*   __restrict__ idx,
                                   const int*   __restrict__ dst,
                                   const float* __restrict__ attn1w,
                                   const float* __restrict__ attn2)
{
    int warp = (blockIdx.x * blockDim.x + threadIdx.x) >> 5;
    int lane = threadIdx.x & 31;
    if (warp >= Ee) return;
    const float* hlast = g_h1;

    int h   = lane >> 2;
    int seg = lane & 3;

    const float* eft = hlast + (size_t)warp * HIDc + h * Dd;
    const float* w2  = attn2  + h * Dd;
    int cidx = idx[warp * Ll + (Ll - 1)];
    const float* ctr = feat + (size_t)cidx * Dd;
    const float* w1  = attn1w + h * Dd;

    float s = 0.f;
#pragma unroll
    for (int q = 0; q < 4; q++) {
        int o = seg * 16 + q * 4;
        float4 ev = *(const float4*)(eft + o);
        float4 wv = *(const float4*)(w2 + o);
        float4 cv = *(const float4*)(ctr + o);
        float4 av = *(const float4*)(w1 + o);
        s += ev.x * wv.x + ev.y * wv.y + ev.z * wv.z + ev.w * wv.w;
        s += cv.x * av.x + cv.y * av.y + cv.z * av.z + cv.w * av.w;
    }
    s += __shfl_down_sync(0xffffffffu, s, 2);
    s += __shfl_down_sync(0xffffffffu, s, 1);

    if (seg == 0) {
        float a = (s > 0.f) ? s : 0.01f * s;
        g_a[(size_t)warp * Hh + h] = a;
        float* addr = &g_amax[(size_t)dst[warp] * Hh + h];
        if (a >= 0.f) atomicMax((int*)addr, __float_as_int(a));
        else          atomicMin((unsigned int*)addr, __float_as_uint(a));
    }
}

// ---------------- exp + denominator -----------------------------------------
__global__ void softmax_norm_kernel(const int* __restrict__ dst) {
    int i = blockIdx.x * blockDim.x + threadIdx.x;
    if (i >= Ee * Hh) return;
    int e = i >> 3, h = i & 7;
    int d = dst[e];
    float ex = __expf(g_a[i] - g_amax[(size_t)d * Hh + h]);
    g_a[i] = ex;
    atomicAdd(&g_den[(size_t)d * Hh + h], ex);
}

// ---------------- weighted segment scatter ----------------------------------
__global__ void scatter_out_kernel(const int* __restrict__ dst,
                                   float* __restrict__ out) {
    int i = blockIdx.x * blockDim.x + threadIdx.x;
    if (i >= Ee * HIDc) return;
    int e = i >> 9, col = i & 511, h = col >> 6;
    int d = dst[e];
    float w = g_a[(size_t)e * Hh + h] / g_den[(size_t)d * Hh + h];
    atomicAdd(out + (size_t)d * HIDc + col, g_h1[i] * w);
}

// ---------------- launch ------------------------------------------------------
extern "C" void kernel_launch(void* const* d_in, const int* in_sizes, int n_in,
                              void* d_out, int out_size)
{
    const float* feat = (const float*)d_in[0];
    const int*   idx  = (const int*)d_in[2];
    const int*   dst  = (const int*)d_in[3];
    const float* Wih  = (const float*)d_in[4];
    const float* Whh  = (const float*)d_in[5];
    const float* bih  = (const float*)d_in[6];
    const float* bhh  = (const float*)d_in[7];
    const float* a1w  = (const float*)d_in[8];
    const float* a2w  = (const float*)d_in[9];
    float* out = (float*)d_out;

    cudaFuncSetAttribute(lstm_mma_kernel,
                         cudaFuncAttributeMaxDynamicSharedMemorySize, DYN_SMEM);

    init_kernel<<<(Nn * HIDc + 255) / 256, 256>>>(out);

    dim3 lgrid((Ee + BM - 1) / BM, HIDc / BNH);   // 782 x 16
    for (int t = 0; t < Ll; t++)
        lstm_mma_kernel<<<lgrid, 256, DYN_SMEM>>>(feat, idx, Wih, Whh, bih, bhh, t);

    attn_logits_kernel<<<(Ee * 32 + 255) / 256, 256>>>(feat, idx, dst, a1w, a2w);
    softmax_norm_kernel<<<(Ee * Hh + 255) / 256, 256>>>(dst);
    scatter_out_kernel<<<(Ee * HIDc + 255) / 256, 256>>>(dst, out);
}

// round 5
// speedup vs baseline: 2.2569x; 2.2569x over previous
#include <cuda_runtime.h>
#include <math.h>
#include <stdint.h>

// Problem constants (fixed-shape problem)
#define Nn   20000
#define Ee   100000
#define Ll   4
#define Dd   64
#define Hh   8
#define HIDc 512

// mma.sync tf32 LSTM tiling
#define BM   128        // edges per CTA
#define BNH  32         // hidden units per CTA -> 128 gate columns
#define BK   32         // K per chunk
#define LDSW 36         // smem row stride in words (32 + 4 pad: conflict-free frags)
#define STAGE_WORDS (2 * BM * LDSW)           // A tile + B tile = 9216 words
#define DYN_SMEM    (2 * STAGE_WORDS * 4)     // 2 stages = 73728 B

// ---------------- scratch (device globals; no allocation allowed) ----------
__device__ float g_h0[(size_t)Ee * HIDc];
__device__ float g_h1[(size_t)Ee * HIDc];
__device__ float g_c [(size_t)Ee * HIDc];
__device__ float g_a [(size_t)Ee * Hh];
__device__ float g_amax[(size_t)Nn * Hh];
__device__ float g_den [(size_t)Nn * Hh];
// tf32-pre-rounded operand copies (fp32 bit patterns, low mantissa zeroed)
__device__ float g_Wih_t [4 * HIDc * Dd];          // 2048 x 64
__device__ float g_Whh_t [(size_t)4 * HIDc * HIDc];// 2048 x 512
__device__ float g_feat_t[(size_t)Nn * Dd];        // 20000 x 64

// ---------------- helpers ----------------------------------------------------
__device__ __forceinline__ uint32_t f2tf(float f) {
    uint32_t r;
    asm("cvt.rna.tf32.f32 %0, %1;" : "=r"(r) : "f"(f));
    return r;
}
__device__ __forceinline__ uint32_t smem_u32(const void* p) {
    uint32_t a;
    asm("{ .reg .u64 t; cvta.to.shared.u64 t, %1; cvt.u32.u64 %0, t; }"
        : "=r"(a) : "l"(p));
    return a;
}
static __device__ __forceinline__ void cpa16(uint32_t dst, const void* src) {
    asm volatile("cp.async.cg.shared.global [%0], [%1], 16;" :: "r"(dst), "l"(src));
}
#define CP_COMMIT() asm volatile("cp.async.commit_group;")
#define CP_WAIT1()  asm volatile("cp.async.wait_group 1;")

__device__ __forceinline__ void mma8(float* d, const uint32_t* a,
                                     uint32_t b0, uint32_t b1) {
    asm volatile(
        "mma.sync.aligned.m16n8k8.row.col.f32.tf32.tf32.f32 "
        "{%0,%1,%2,%3}, {%4,%5,%6,%7}, {%8,%9}, {%0,%1,%2,%3};"
        : "+f"(d[0]), "+f"(d[1]), "+f"(d[2]), "+f"(d[3])
        : "r"(a[0]), "r"(a[1]), "r"(a[2]), "r"(a[3]), "r"(b0), "r"(b1));
}

// ---------------- prep: tf32-round weights + features once -------------------
__global__ void prep_kernel(const float* __restrict__ Wih,
                            const float* __restrict__ Whh,
                            const float* __restrict__ feat) {
    int i = blockIdx.x * blockDim.x + threadIdx.x;
    if (i < 4 * HIDc * Dd)   g_Wih_t[i]  = __uint_as_float(f2tf(Wih[i]));
    if (i < 4 * HIDc * HIDc) g_Whh_t[i]  = __uint_as_float(f2tf(Whh[i]));
    if (i < Nn * Dd)         g_feat_t[i] = __uint_as_float(f2tf(feat[i]));
}

// ---------------- init -------------------------------------------------------
__global__ void init_kernel(float* __restrict__ out) {
    int i = blockIdx.x * blockDim.x + threadIdx.x;
    if (i < Nn * HIDc) out[i] = 0.f;
    if (i < Nn * Hh) {
        g_amax[i] = __int_as_float(0xFF800000);
        g_den[i]  = 0.f;
    }
}

// ---------------- tensor-core (mma.sync tf32) LSTM step ----------------------
// gates(E x 2048) = x_t @ W_ih^T + h_prev @ W_hh^T (+bias in epilogue).
// CTA: 128 edges x 32 hidden (x4 gates = 128 gate cols), K double-buffered by 32
// via cp.async from pre-rounded tf32 buffers (no reg staging, no cvt in loop).
// 2 CTAs/SM (regs<=128, 72KB smem each). Warp = 32 rows x 16 hidden x 4 gates.
__global__ __launch_bounds__(256, 2)
void lstm_mma_kernel(const int*   __restrict__ idx,
                     const float* __restrict__ bih,
                     const float* __restrict__ bhh,
                     int t)
{
    extern __shared__ uint32_t smem[];
    __shared__ int   rows_s[BM];
    __shared__ float bias_s[128];

    const int tid   = threadIdx.x;
    const int wid   = tid >> 5;
    const int lane  = tid & 31;
    const int warpM = wid & 3;        // 0..3 (rows)
    const int warpN = wid >> 2;       // 0..1 (hidden halves)
    const int e0    = blockIdx.x * BM;
    const int nh0   = blockIdx.y * BNH;

    const float* hprev = (t & 1) ? g_h0 : g_h1;
    float*       hnext = (t & 1) ? g_h1 : g_h0;
    const bool   first = (t == 0);
    const int    NC    = first ? 2 : 18;      // K chunks: 64 feat (+512 hidden)

    if (tid < BM) {
        int e = e0 + tid; if (e >= Ee) e = Ee - 1;
        rows_s[tid] = idx[e * Ll + t];
    }
    if (tid < 128) {   // bias, c = g*32 + hh
        int g = tid >> 5, hh = tid & 31;
        int r = g * HIDc + nh0 + hh;
        bias_s[tid] = bih[r] + bhh[r];
    }
    __syncthreads();   // rows_s ready before first cp.async fill

    // fill-lane mapping: row r, k-half (16 floats = 4x16B each for A and B)
    const int r     = tid & 127;
    const int k0loc = (tid >> 7) * 16;
    const int wrow  = (r >> 5) * HIDc + nh0 + (r & 31);
    const uint32_t smem_base = smem_u32(smem);
    int eA = e0 + r; if (eA >= Ee) eA = Ee - 1;

    auto fill = [&](int kc) {
        const int s = kc & 1;
        uint32_t abase = smem_base + (uint32_t)(s * STAGE_WORDS + r * LDSW + k0loc) * 4u;
        uint32_t bbase = abase + (uint32_t)(BM * LDSW) * 4u;
        const float* ap = (kc < 2)
            ? g_feat_t + (size_t)rows_s[r] * Dd + kc * BK + k0loc
            : hprev    + (size_t)eA * HIDc + (kc - 2) * BK + k0loc;
        const float* bp = (kc < 2)
            ? g_Wih_t + (size_t)wrow * Dd   + kc * BK + k0loc
            : g_Whh_t + (size_t)wrow * HIDc + (kc - 2) * BK + k0loc;
#pragma unroll
        for (int q = 0; q < 4; q++) {
            cpa16(abase + q * 16, ap + q * 4);
            cpa16(bbase + q * 16, bp + q * 4);
        }
    };

    float acc[2][2][4][4];
#pragma unroll
    for (int mb = 0; mb < 2; mb++)
#pragma unroll
        for (int nb = 0; nb < 2; nb++)
#pragma unroll
            for (int g = 0; g < 4; g++)
#pragma unroll
                for (int v = 0; v < 4; v++) acc[mb][nb][g][v] = 0.f;

    // prologue: fill stages 0 and 1
    fill(0); CP_COMMIT();
    if (NC > 1) fill(1);
    CP_COMMIT();
    CP_WAIT1();
    __syncthreads();

    const int arow = warpM * 32 + (lane >> 2);
    const int kl   = lane & 3;

    for (int kc = 0; kc < NC; kc++) {
        const int buf = kc & 1;
        const uint32_t* Ab = smem + buf * STAGE_WORDS;
        const uint32_t* Bb = Ab + BM * LDSW;
#pragma unroll
        for (int kk = 0; kk < 4; kk++) {
            uint32_t afr[2][4];
#pragma unroll
            for (int mb = 0; mb < 2; mb++) {
                const uint32_t* A0 = Ab + (arow + mb * 16) * LDSW + kk * 8 + kl;
                afr[mb][0] = A0[0];
                afr[mb][1] = A0[8 * LDSW];
                afr[mb][2] = A0[4];
                afr[mb][3] = A0[8 * LDSW + 4];
            }
#pragma unroll
            for (int nb = 0; nb < 2; nb++) {
                int colb = warpN * 16 + nb * 8 + (lane >> 2);
#pragma unroll
                for (int g = 0; g < 4; g++) {
                    const uint32_t* B0 = Bb + (g * 32 + colb) * LDSW + kk * 8 + kl;
                    uint32_t b0 = B0[0], b1 = B0[4];
                    mma8(acc[0][nb][g], afr[0], b0, b1);
                    mma8(acc[1][nb][g], afr[1], b0, b1);
                }
            }
        }
        if (kc + 1 < NC) {
            __syncthreads();               // all warps done reading buf
            if (kc + 2 < NC) fill(kc + 2); // refill this buf
            CP_COMMIT();
            CP_WAIT1();                    // stage kc+1 resident
            __syncthreads();
        }
    }

    // ---- epilogue: LSTM cell from accumulators ------------------------------
#pragma unroll
    for (int mb = 0; mb < 2; mb++) {
#pragma unroll
        for (int rh = 0; rh < 2; rh++) {
            int e = e0 + warpM * 32 + mb * 16 + (lane >> 2) + rh * 8;
            if (e >= Ee) continue;
            float* cp = g_c   + (size_t)e * HIDc + nh0;
            float* hp = hnext + (size_t)e * HIDc + nh0;
#pragma unroll
            for (int nb = 0; nb < 2; nb++) {
                int hh = warpN * 16 + nb * 8 + (lane & 3) * 2;
                float2 cold = make_float2(0.f, 0.f);
                if (!first) cold = *(const float2*)(cp + hh);
                float cv[2], hv[2];
#pragma unroll
                for (int v = 0; v < 2; v++) {
                    int ci = rh * 2 + v;
                    float gi = acc[mb][nb][0][ci] + bias_s[      hh + v];
                    float gf = acc[mb][nb][1][ci] + bias_s[ 32 + hh + v];
                    float gg = acc[mb][nb][2][ci] + bias_s[ 64 + hh + v];
                    float go = acc[mb][nb][3][ci] + bias_s[ 96 + hh + v];
                    float si = 1.f / (1.f + __expf(-gi));
                    float sf = 1.f / (1.f + __expf(-gf));
                    float tg = tanhf(gg);
                    float so = 1.f / (1.f + __expf(-go));
                    float co = v ? cold.y : cold.x;
                    float cn = sf * co + si * tg;
                    cv[v] = cn;
                    // h stored pre-rounded to tf32 so next step cp.asyncs it raw
                    hv[v] = __uint_as_float(f2tf(so * tanhf(cn)));
                }
                *(float2*)(cp + hh) = make_float2(cv[0], cv[1]);
                *(float2*)(hp + hh) = make_float2(hv[0], hv[1]);
            }
        }
    }
}

// ---------------- attention logits + segment max (warp per edge) -----------
__global__ void attn_logits_kernel(const float* __restrict__ feat,
                                   const int*   __restrict__ idx,
                                   const int*   __restrict__ dst,
                                   const float* __restrict__ attn1w,
                                   const float* __restrict__ attn2)
{
    int warp = (blockIdx.x * blockDim.x + threadIdx.x) >> 5;
    int lane = threadIdx.x & 31;
    if (warp >= Ee) return;
    const float* hlast = g_h1;

    int h   = lane >> 2;
    int seg = lane & 3;

    const float* eft = hlast + (size_t)warp * HIDc + h * Dd;
    const float* w2  = attn2  + h * Dd;
    int cidx = idx[warp * Ll + (Ll - 1)];
    const float* ctr = feat + (size_t)cidx * Dd;
    const float* w1  = attn1w + h * Dd;

    float s = 0.f;
#pragma unroll
    for (int q = 0; q < 4; q++) {
        int o = seg * 16 + q * 4;
        float4 ev = *(const float4*)(eft + o);
        float4 wv = *(const float4*)(w2 + o);
        float4 cv = *(const float4*)(ctr + o);
        float4 av = *(const float4*)(w1 + o);
        s += ev.x * wv.x + ev.y * wv.y + ev.z * wv.z + ev.w * wv.w;
        s += cv.x * av.x + cv.y * av.y + cv.z * av.z + cv.w * av.w;
    }
    s += __shfl_down_sync(0xffffffffu, s, 2);
    s += __shfl_down_sync(0xffffffffu, s, 1);

    if (seg == 0) {
        float a = (s > 0.f) ? s : 0.01f * s;
        g_a[(size_t)warp * Hh + h] = a;
        float* addr = &g_amax[(size_t)dst[warp] * Hh + h];
        if (a >= 0.f) atomicMax((int*)addr, __float_as_int(a));
        else          atomicMin((unsigned int*)addr, __float_as_uint(a));
    }
}

// ---------------- exp + denominator -----------------------------------------
__global__ void softmax_norm_kernel(const int* __restrict__ dst) {
    int i = blockIdx.x * blockDim.x + threadIdx.x;
    if (i >= Ee * Hh) return;
    int e = i >> 3, h = i & 7;
    int d = dst[e];
    float ex = __expf(g_a[i] - g_amax[(size_t)d * Hh + h]);
    g_a[i] = ex;
    atomicAdd(&g_den[(size_t)d * Hh + h], ex);
}

// ---------------- weighted segment scatter ----------------------------------
__global__ void scatter_out_kernel(const int* __restrict__ dst,
                                   float* __restrict__ out) {
    int i = blockIdx.x * blockDim.x + threadIdx.x;
    if (i >= Ee * HIDc) return;
    int e = i >> 9, col = i & 511, h = col >> 6;
    int d = dst[e];
    float w = g_a[(size_t)e * Hh + h] / g_den[(size_t)d * Hh + h];
    atomicAdd(out + (size_t)d * HIDc + col, g_h1[i] * w);
}

// ---------------- launch ------------------------------------------------------
extern "C" void kernel_launch(void* const* d_in, const int* in_sizes, int n_in,
                              void* d_out, int out_size)
{
    const float* feat = (const float*)d_in[0];
    const int*   idx  = (const int*)d_in[2];
    const int*   dst  = (const int*)d_in[3];
    const float* Wih  = (const float*)d_in[4];
    const float* Whh  = (const float*)d_in[5];
    const float* bih  = (const float*)d_in[6];
    const float* bhh  = (const float*)d_in[7];
    const float* a1w  = (const float*)d_in[8];
    const float* a2w  = (const float*)d_in[9];
    float* out = (float*)d_out;

    cudaFuncSetAttribute(lstm_mma_kernel,
                         cudaFuncAttributeMaxDynamicSharedMemorySize, DYN_SMEM);

    prep_kernel<<<(Nn * Dd + 255) / 256, 256>>>(Wih, Whh, feat);
    init_kernel<<<(Nn * HIDc + 255) / 256, 256>>>(out);

    dim3 lgrid((Ee + BM - 1) / BM, HIDc / BNH);   // 782 x 16
    for (int t = 0; t < Ll; t++)
        lstm_mma_kernel<<<lgrid, 256, DYN_SMEM>>>(idx, bih, bhh, t);

    attn_logits_kernel<<<(Ee * 32 + 255) / 256, 256>>>(feat, idx, dst, a1w, a2w);
    softmax_norm_kernel<<<(Ee * Hh + 255) / 256, 256>>>(dst);
    scatter_out_kernel<<<(Ee * HIDc + 255) / 256, 256>>>(dst, out);
}